// round 15
// baseline (speedup 1.0000x reference)
#include <cuda_runtime.h>
#include <cuda_fp16.h>
#include <math.h>

#define B_SZ 4
#define T_SZ 2048
#define DM   1024
#define NH   16
#define DH   64
#define HALF 32   // DH/2

typedef unsigned int u32;

// ---------------- scratch (device globals; no runtime allocation) ----------------
__device__ float g_cos[T_SZ*HALF];
__device__ float g_sin[T_SZ*HALF];
__device__ float g_pm[64*4*32];
__device__ float g_pl[64*4*32];
__device__ float g_pacc[64*4*32*64];
// fp16 operands
__device__ __half g_xh[B_SZ*T_SZ*DM];
__device__ __half g_wqh[DM*3*DM];
__device__ __half g_woh[DM*DM];
__device__ __half g_ah[B_SZ*T_SZ*DM];     // attention output (fp16), input to out-proj
// fp16 q/k/v (RoPE applied)
__device__ __half g_qf16[B_SZ*NH*T_SZ*DH];
__device__ __half g_kf16[B_SZ*NH*T_SZ*DH];
__device__ __half g_vf16[B_SZ*NH*T_SZ*DH];

// ---------------- GEMM tiling constants (KS=32, 3 stages, 2 CTA/SM) -------------
#define KS        32
#define NSTG      3
// A: 128 rows x 40 halfs (80B) = 10240B ; B: 32 rows x 136 halfs (272B) = 8704B
#define A_OFF     0
#define B_OFF     10240
#define STG_BYTES 18944
#define GEMM_SMEM (NSTG * STG_BYTES)   // 56832

// attention smem (halfs): Q[128][72] | K[64][72] | V[64][72]
#define AQ_OFF 0
#define AK_OFF 9216
#define AV_OFF 13824
#define ATTN_SMEM 49152

// ---------------- tensor-core / async helpers ----------------
__device__ __forceinline__ void ldsm4(u32& r0, u32& r1, u32& r2, u32& r3, u32 a) {
    asm volatile("ldmatrix.sync.aligned.m8n8.x4.shared.b16 {%0,%1,%2,%3}, [%4];"
                 : "=r"(r0), "=r"(r1), "=r"(r2), "=r"(r3) : "r"(a));
}
__device__ __forceinline__ void ldsm4t(u32& r0, u32& r1, u32& r2, u32& r3, u32 a) {
    asm volatile("ldmatrix.sync.aligned.m8n8.x4.trans.shared.b16 {%0,%1,%2,%3}, [%4];"
                 : "=r"(r0), "=r"(r1), "=r"(r2), "=r"(r3) : "r"(a));
}
__device__ __forceinline__ void mma_f16(float* d, const u32* a, const u32* b) {
    asm volatile("mma.sync.aligned.m16n8k16.row.col.f32.f16.f16.f32 "
                 "{%0,%1,%2,%3}, {%4,%5,%6,%7}, {%8,%9}, {%0,%1,%2,%3};"
                 : "+f"(d[0]), "+f"(d[1]), "+f"(d[2]), "+f"(d[3])
                 : "r"(a[0]), "r"(a[1]), "r"(a[2]), "r"(a[3]), "r"(b[0]), "r"(b[1]));
}
__device__ __forceinline__ void cpa16(u32 dst, const void* src) {
    asm volatile("cp.async.cg.shared.global [%0], [%1], 16;" :: "r"(dst), "l"(src) : "memory");
}
__device__ __forceinline__ void cpa_commit() {
    asm volatile("cp.async.commit_group;" ::: "memory");
}
template<int N> __device__ __forceinline__ void cpa_wait() {
    asm volatile("cp.async.wait_group %0;" :: "n"(N) : "memory");
}

// ---------------- cvt kernel: fp32 -> fp16, 8 elems/thread ----------------
__global__ void cvt_f16_kernel(const float* __restrict__ src,
                               __half* __restrict__ dst, int n8) {
    int i = blockIdx.x * blockDim.x + threadIdx.x;
    if (i >= n8) return;
    float4 v0 = ((const float4*)src)[2*i];
    float4 v1 = ((const float4*)src)[2*i + 1];
    __half2 h0 = __floats2half2_rn(v0.x, v0.y);
    __half2 h1 = __floats2half2_rn(v0.z, v0.w);
    __half2 h2 = __floats2half2_rn(v1.x, v1.y);
    __half2 h3 = __floats2half2_rn(v1.z, v1.w);
    ((uint4*)dst)[i] = make_uint4(*(u32*)&h0, *(u32*)&h1, *(u32*)&h2, *(u32*)&h3);
}

// ---------------- kernel 0: RoPE tables ----------------
__global__ void rope_table_kernel() {
    int idx = blockIdx.x * blockDim.x + threadIdx.x;
    if (idx >= T_SZ * HALF) return;
    int t = idx / HALF;
    int j = idx % HALF;
    double inv = pow(10000.0, -(double)j / (double)HALF);
    double ang = (double)t * inv;
    g_cos[idx] = (float)cos(ang);
    g_sin[idx] = (float)sin(ang);
}

// ---------------- 128x128 fp16 GEMM, 256 thr, KS=32, 3-stage ----------------
// 8 warps in 2x4 grid; warp tile 64x32 (mi 4 x ni 4 m16n8 frags), 2 k16 halves/step.
template<int LDB>
__device__ __forceinline__ void tc_gemm_f16(
    const __half* __restrict__ Ag, const __half* __restrict__ Bg,
    float (&acc)[4][4][4])
{
    extern __shared__ char sm[];
    const u32 smb = (u32)__cvta_generic_to_shared(sm);
    const int tid  = threadIdx.x;
    const int lane = tid & 31;
    const int warp = tid >> 5;
    const int wm = warp >> 2;
    const int wn = warp & 3;
    const int arow = (lane & 7) + ((lane >> 3) & 1) * 8;
    const int akk  = ((lane >> 4) & 1) * 8;

    const int ar = tid >> 1;              // A row 0..127
    const int ac = (tid & 1) * 16;        // A half-offset within 32-elem k-step
    const int br = tid >> 3;              // B k-row 0..31
    const int bc = (tid & 7) * 16;        // B col chunk

#pragma unroll
    for (int mi = 0; mi < 4; mi++)
#pragma unroll
        for (int ni = 0; ni < 4; ni++)
#pragma unroll
            for (int r = 0; r < 4; r++)
                acc[mi][ni][r] = 0.f;

    const u32 a_soff = (u32)(ar * 80 + ac * 2);
    const u32 b_soff = (u32)(br * 272 + bc * 2);

#define ISSUE_STAGE(kt, st) do {                                                   \
        const u32 sb = smb + (u32)(st) * STG_BYTES;                                \
        const __half* ap = Ag + (size_t)ar * DM + (kt) * KS + ac;                  \
        const __half* bp = Bg + (size_t)((kt) * KS + br) * LDB + bc;               \
        cpa16(sb + A_OFF + a_soff,      ap);                                       \
        cpa16(sb + A_OFF + a_soff + 16, ap + 8);                                   \
        cpa16(sb + B_OFF + b_soff,      bp);                                       \
        cpa16(sb + B_OFF + b_soff + 16, bp + 8);                                   \
        cpa_commit();                                                              \
    } while (0)

    ISSUE_STAGE(0, 0);
    ISSUE_STAGE(1, 1);

    const int KT = DM / KS;               // 32
    for (int kt = 0; kt < KT; kt++) {
        if (kt == KT - 1) cpa_wait<0>(); else cpa_wait<1>();
        __syncthreads();
        if (kt + 2 < KT) ISSUE_STAGE(kt + 2, (kt + 2) % NSTG);

        const u32 sb = smb + (u32)(kt % NSTG) * STG_BYTES;
#pragma unroll
        for (int kh = 0; kh < 2; kh++) {
            const u32 abase = sb + A_OFF + (u32)((wm*64 + arow) * 80 + (kh*16 + akk) * 2);
            const u32 bbase = sb + B_OFF + (u32)((kh*16 + arow) * 272 + (wn*32 + akk) * 2);

            u32 A[4][4];
            u32 B[4][2];
#pragma unroll
            for (int mi = 0; mi < 4; mi++)
                ldsm4(A[mi][0], A[mi][1], A[mi][2], A[mi][3], abase + (u32)(mi * 16 * 80));
#pragma unroll
            for (int nj = 0; nj < 2; nj++) {
                u32 t0, t1, t2, t3;
                ldsm4t(t0, t1, t2, t3, bbase + (u32)(nj * 32));
                B[nj*2][0] = t0;
                B[nj*2][1] = t1;
                B[nj*2+1][0] = t2;
                B[nj*2+1][1] = t3;
            }
#pragma unroll
            for (int mi = 0; mi < 4; mi++)
#pragma unroll
                for (int ni = 0; ni < 4; ni++)
                    mma_f16(acc[mi][ni], A[mi], B[ni]);
        }
    }
#undef ISSUE_STAGE
}

// ---------------- kernel 1: QKV GEMM + RoPE epilogue (fp16 outputs only) --------
__global__ __launch_bounds__(256, 2) void qkv_tc_kernel() {
    const int row0 = blockIdx.y * 128;
    const int col0 = blockIdx.x * 128;
    float acc[4][4][4];
    tc_gemm_f16<3072>(g_xh + (size_t)row0 * DM, g_wqh + col0, acc);

    const int lane = threadIdx.x & 31;
    const int warp = threadIdx.x >> 5;
    const int wm = warp >> 2;
    const int wn = warp & 3;
    const int r0c = lane >> 2;
    const int cp  = (lane & 3) * 2;
    const int which = col0 >> 10;
    __half* dsth = (which == 0) ? g_qf16 : ((which == 1) ? g_kf16 : g_vf16);
    const bool dorope = (which < 2);

#pragma unroll
    for (int mi = 0; mi < 4; mi++) {
#pragma unroll
        for (int half = 0; half < 2; half++) {
            const int gm = row0 + wm*64 + mi*16 + r0c + half*8;
            const int bb = gm >> 11;
            const int t  = gm & (T_SZ - 1);
#pragma unroll
            for (int ni = 0; ni < 4; ni++) {
                const int gn  = col0 + wn*32 + ni*8 + cp;
                const int rem = gn & 1023;
                const int h = rem >> 6;
                const int d = rem & 63;
                float v0 = acc[mi][ni][half*2 + 0];
                float v1 = acc[mi][ni][half*2 + 1];
                if (dorope) {
                    const int j = d >> 1;
                    const float c = g_cos[t*HALF + j];
                    const float s = g_sin[t*HALF + j];
                    const float re = v0*c - v1*s;
                    const float ro = v0*s + v1*c;
                    v0 = re;
                    v1 = ro;
                }
                const size_t idx = ((size_t)(bb*NH + h) * T_SZ + t) * DH + d;
                __half2 hp = __floats2half2_rn(v0, v1);
                *(u32*)&dsth[idx] = *(u32*)&hp;
            }
        }
    }
}

// ---------------- kernel 3: out projection + bias ----------------
__global__ __launch_bounds__(256, 2) void out_tc_kernel(const float* __restrict__ bias,
                                                        float* __restrict__ out) {
    const int row0 = blockIdx.y * 128;
    const int col0 = blockIdx.x * 128;
    float acc[4][4][4];
    tc_gemm_f16<1024>(g_ah + (size_t)row0 * DM, g_woh + col0, acc);

    const int lane = threadIdx.x & 31;
    const int warp = threadIdx.x >> 5;
    const int wm = warp >> 2;
    const int wn = warp & 3;
    const int r0c = lane >> 2;
    const int cp  = (lane & 3) * 2;

#pragma unroll
    for (int mi = 0; mi < 4; mi++) {
#pragma unroll
        for (int half = 0; half < 2; half++) {
            const int gm = row0 + wm*64 + mi*16 + r0c + half*8;
#pragma unroll
            for (int ni = 0; ni < 4; ni++) {
                const int gn = col0 + wn*32 + ni*8 + cp;
                const float b0 = bias[gn];
                const float b1 = bias[gn + 1];
                *(float2*)&out[(size_t)gm * DM + gn] =
                    make_float2(acc[mi][ni][half*2 + 0] + b0,
                                acc[mi][ni][half*2 + 1] + b1);
            }
        }
    }
}

// ---------------- fused attention ----------------
// Blocks [0,1024): tensor-core sparse flash, fp16 in/out.
// Blocks [1024,1280): global-query split-K partials (fp16 in, fp32 math).
__global__ __launch_bounds__(256) void attn_fused_kernel() {
    extern __shared__ float smf[];
    const int bid = blockIdx.x;
    const int tid = threadIdx.x;

    if (bid < 1024) {
        __half* smh = (__half*)smf;
        const u32 smb = (u32)__cvta_generic_to_shared(smh);
        const int p  = bid & 15;
        const int bh = bid >> 4;
        const int lane = tid & 31;
        const int warp = tid >> 5;
        const int group = warp >> 2;
        const int mb    = warp & 3;
        const int qt    = 2*p + group;
        const int arow  = (lane & 7) + ((lane >> 3) & 1) * 8;
        const int akk8  = ((lane >> 4) & 1) * 8;

        const __half* qhp = g_qf16 + (size_t)(bh * T_SZ + p * 128) * DH;
        const __half* khp = g_kf16 + (size_t)bh * T_SZ * DH;
        const __half* vhp = g_vf16 + (size_t)bh * T_SZ * DH;

        for (int i = 0; i < 4; i++) {
            const int idx = tid + i * 256;
            const int row = idx >> 3;
            const int ch  = idx & 7;
            *(uint4*)&smh[AQ_OFF + row * 72 + ch * 8] =
                *(const uint4*)&qhp[row * 64 + ch * 8];
        }
        __syncthreads();

        u32 QA[4][4];
        {
            const u32 qb = smb + (u32)(2 * (AQ_OFF + (group*64 + mb*16 + arow) * 72));
#pragma unroll
            for (int kc = 0; kc < 4; kc++)
                ldsm4(QA[kc][0], QA[kc][1], QA[kc][2], QA[kc][3],
                      qb + (u32)(2 * (kc * 16 + akk8)));
        }

        float m[2] = {-1e30f, -1e30f};
        float l[2] = {0.f, 0.f};
        float O[8][4];
#pragma unroll
        for (int nf = 0; nf < 8; nf++)
#pragma unroll
            for (int e = 0; e < 4; e++) O[nf][e] = 0.f;

        const int jmax_w = qt - 3;
        const int jmax_pair = 2*p - 2;
        const int ktlo = (2*p >= 2) ? (2*p - 2) : 0;
        const int n_iter = (2*p + 1) - ktlo + 1 + (p >= 1 ? 1 : 0);

        for (int it = 0; it < n_iter; it++) {
            const bool global_tile = (p >= 1) && (it == 0);
            const int kt = global_tile ? -1 : (ktlo + it - (p >= 1 ? 1 : 0));
            __syncthreads();
            for (int i = 0; i < 4; i++) {
                const int idx = tid + i * 256;
                const bool isV = idx >= 512;
                const int ri = (idx & 511) >> 3;
                const int ch = idx & 7;
                const int off = (isV ? AV_OFF : AK_OFF) + ri * 72 + ch * 8;
                const __half* src = isV ? vhp : khp;
                if (global_tile) {
                    if (ri <= jmax_pair)
                        *(uint4*)&smh[off] = *(const uint4*)&src[(ri << 6) * 64 + ch * 8];
                    else
                        *(uint4*)&smh[off] = make_uint4(0, 0, 0, 0);
                } else {
                    *(uint4*)&smh[off] = *(const uint4*)&src[(kt * 64 + ri) * 64 + ch * 8];
                }
            }
            __syncthreads();

            const bool active = global_tile ? (jmax_w >= 0)
                                            : (kt >= qt - 2 && kt <= qt);
            if (!active) continue;

            float C[8][4];
#pragma unroll
            for (int nf = 0; nf < 8; nf++)
#pragma unroll
                for (int e = 0; e < 4; e++) C[nf][e] = 0.f;
#pragma unroll
            for (int nb = 0; nb < 4; nb++) {
                const u32 kb = smb + (u32)(2 * (AK_OFF + (nb*16 + arow) * 72));
#pragma unroll
                for (int kc = 0; kc < 4; kc++) {
                    u32 t0, t1, t2, t3;
                    ldsm4(t0, t1, t2, t3, kb + (u32)(2 * (kc * 16 + akk8)));
                    u32 b0[2] = {t0, t2};
                    u32 b1[2] = {t1, t3};
                    mma_f16(C[2*nb],     QA[kc], b0);
                    mma_f16(C[2*nb + 1], QA[kc], b1);
                }
            }

            const int rbase = qt * 64 + mb * 16 + (lane >> 2);
            const int cbase = (lane & 3) * 2;
#pragma unroll
            for (int nf = 0; nf < 8; nf++) {
#pragma unroll
                for (int e = 0; e < 4; e++) {
                    const int q = rbase + (e >> 1) * 8;
                    const int col = nf * 8 + cbase + (e & 1);
                    bool ok;
                    if (global_tile) {
                        ok = (col <= jmax_w);
                    } else {
                        const int k = kt * 64 + col;
                        ok = (k <= q) && ((q - k) <= 127 || ((k & 63) == 0) || ((q & 63) == 0));
                    }
                    C[nf][e] = ok ? C[nf][e] * 0.125f : -1.0e9f;
                }
            }

            float rm[2] = {-1e30f, -1e30f};
#pragma unroll
            for (int nf = 0; nf < 8; nf++) {
                rm[0] = fmaxf(rm[0], fmaxf(C[nf][0], C[nf][1]));
                rm[1] = fmaxf(rm[1], fmaxf(C[nf][2], C[nf][3]));
            }
#pragma unroll
            for (int off = 1; off <= 2; off <<= 1) {
                rm[0] = fmaxf(rm[0], __shfl_xor_sync(0xffffffffu, rm[0], off));
                rm[1] = fmaxf(rm[1], __shfl_xor_sync(0xffffffffu, rm[1], off));
            }

            float sc[2];
#pragma unroll
            for (int i = 0; i < 2; i++) {
                const float mn = fmaxf(m[i], rm[i]);
                sc[i] = __expf(m[i] - mn);
                m[i] = mn;
            }
            float rs[2] = {0.f, 0.f};
#pragma unroll
            for (int nf = 0; nf < 8; nf++) {
                C[nf][0] = __expf(C[nf][0] - m[0]);
                C[nf][1] = __expf(C[nf][1] - m[0]);
                C[nf][2] = __expf(C[nf][2] - m[1]);
                C[nf][3] = __expf(C[nf][3] - m[1]);
                rs[0] += C[nf][0] + C[nf][1];
                rs[1] += C[nf][2] + C[nf][3];
            }
#pragma unroll
            for (int off = 1; off <= 2; off <<= 1) {
                rs[0] += __shfl_xor_sync(0xffffffffu, rs[0], off);
                rs[1] += __shfl_xor_sync(0xffffffffu, rs[1], off);
            }
#pragma unroll
            for (int i = 0; i < 2; i++) l[i] = l[i] * sc[i] + rs[i];
#pragma unroll
            for (int nf = 0; nf < 8; nf++) {
                O[nf][0] *= sc[0];
                O[nf][1] *= sc[0];
                O[nf][2] *= sc[1];
                O[nf][3] *= sc[1];
            }

            u32 PA[4][4];
#pragma unroll
            for (int j = 0; j < 4; j++) {
                __half2 h0 = __floats2half2_rn(C[2*j][0],   C[2*j][1]);
                __half2 h1 = __floats2half2_rn(C[2*j][2],   C[2*j][3]);
                __half2 h2 = __floats2half2_rn(C[2*j+1][0], C[2*j+1][1]);
                __half2 h3 = __floats2half2_rn(C[2*j+1][2], C[2*j+1][3]);
                PA[j][0] = *(u32*)&h0;
                PA[j][1] = *(u32*)&h1;
                PA[j][2] = *(u32*)&h2;
                PA[j][3] = *(u32*)&h3;
            }

#pragma unroll
            for (int kc = 0; kc < 4; kc++) {
                const u32 vb = smb + (u32)(2 * (AV_OFF + (kc*16 + arow) * 72));
#pragma unroll
                for (int db = 0; db < 4; db++) {
                    u32 t0, t1, t2, t3;
                    ldsm4t(t0, t1, t2, t3, vb + (u32)(2 * (db * 16 + akk8)));
                    u32 b0[2] = {t0, t1};
                    u32 b1[2] = {t2, t3};
                    mma_f16(O[2*db],     PA[kc], b0);
                    mma_f16(O[2*db + 1], PA[kc], b1);
                }
            }
        }

        // normalize + store fp16 directly into g_ah [B,T,C]
        const int bb = bh >> 4;
        const int hh = bh & 15;
        const float inv0 = 1.f / l[0];
        const float inv1 = 1.f / l[1];
        const int r0 = qt * 64 + mb * 16 + (lane >> 2);
        const int c0 = (lane & 3) * 2;
#pragma unroll
        for (int nf = 0; nf < 8; nf++) {
            const int d = nf * 8 + c0;
            __half2 p0 = __floats2half2_rn(O[nf][0] * inv0, O[nf][1] * inv0);
            __half2 p1 = __floats2half2_rn(O[nf][2] * inv1, O[nf][3] * inv1);
            *(u32*)&g_ah[((size_t)(bb * T_SZ + r0) * DM) + hh * 64 + d] = *(u32*)&p0;
            *(u32*)&g_ah[((size_t)(bb * T_SZ + r0 + 8) * DM) + hh * 64 + d] = *(u32*)&p1;
        }
        return;
    }

    // ---- global-query split-K partials (fp16 inputs, fp32 math) ----
    {
        const int tx = tid & 15, ty = tid >> 4;
        float (*Qs2)[32] = (float(*)[32])smf;
        float (*KP)[64]  = (float(*)[64])(smf + 64*32);
        float (*Vs)[64]  = (float(*)[64])(smf + 64*32 + 64*64);
        const int id = bid - 1024;
        const int bh = id >> 2;
        const int kc = id & 3;
        const __half* qbase = g_qf16 + (size_t)bh * T_SZ * DH;
        const __half* kbase = g_kf16 + (size_t)bh * T_SZ * DH;
        const __half* vbase = g_vf16 + (size_t)bh * T_SZ * DH;

        {
            const int r  = tid >> 3;
            const int d0 = (tid & 7) * 8;
            uint4 raw = *(const uint4*)&qbase[(r << 6) * DH + d0];
            const __half2* hp = (const __half2*)&raw;
#pragma unroll
            for (int j = 0; j < 4; j++) {
                float2 f = __half22float2(hp[j]);
                Qs2[d0 + 2*j][r]     = f.x;
                Qs2[d0 + 2*j + 1][r] = f.y;
            }
        }

        float m[2] = {-1e30f, -1e30f}, l[2] = {0.f, 0.f};
        float acc[2][4];
#pragma unroll
        for (int i = 0; i < 2; i++)
#pragma unroll
            for (int j = 0; j < 4; j++) acc[i][j] = 0.f;

        for (int it = 0; it < 8; it++) {
            const int kt = kc * 8 + it;
            __syncthreads();
            {
                const int row = tid >> 2;
                const int cc  = tid & 3;
#pragma unroll
                for (int u = 0; u < 4; u++) {
                    const int d0 = (cc + 4 * u) * 4;
                    uint2 kraw = *(const uint2*)&kbase[(kt * 64 + row) * DH + d0];
                    const __half2* kp = (const __half2*)&kraw;
                    float2 k0 = __half22float2(kp[0]);
                    float2 k1 = __half22float2(kp[1]);
                    KP[d0+0][row] = k0.x; KP[d0+1][row] = k0.y;
                    KP[d0+2][row] = k1.x; KP[d0+3][row] = k1.y;
                    uint2 vraw = *(const uint2*)&vbase[(kt * 64 + row) * DH + d0];
                    const __half2* vp = (const __half2*)&vraw;
                    float2 vv0 = __half22float2(vp[0]);
                    float2 vv1 = __half22float2(vp[1]);
                    *(float4*)&Vs[row][d0] = make_float4(vv0.x, vv0.y, vv1.x, vv1.y);
                }
            }
            __syncthreads();

            float s[2][4];
#pragma unroll
            for (int i = 0; i < 2; i++)
#pragma unroll
                for (int j = 0; j < 4; j++) s[i][j] = 0.f;
#pragma unroll 16
            for (int d = 0; d < 64; d++) {
                const float a0 = Qs2[d][ty*2];
                const float a1 = Qs2[d][ty*2 + 1];
                float4 b = *(float4*)&KP[d][tx*4];
                float br[4] = {b.x, b.y, b.z, b.w};
#pragma unroll
                for (int j = 0; j < 4; j++) {
                    s[0][j] = fmaf(a0, br[j], s[0][j]);
                    s[1][j] = fmaf(a1, br[j], s[1][j]);
                }
            }
#pragma unroll
            for (int i = 0; i < 2; i++) {
                const int qv = (ty*2 + i) << 6;
#pragma unroll
                for (int j = 0; j < 4; j++) {
                    const int k = kt * 64 + tx*4 + j;
                    s[i][j] = (k <= qv) ? s[i][j] * 0.125f : -1.0e9f;
                }
            }

            float rm[2];
#pragma unroll
            for (int i = 0; i < 2; i++)
                rm[i] = fmaxf(fmaxf(s[i][0], s[i][1]), fmaxf(s[i][2], s[i][3]));
#pragma unroll
            for (int off = 8; off > 0; off >>= 1)
#pragma unroll
                for (int i = 0; i < 2; i++)
                    rm[i] = fmaxf(rm[i], __shfl_xor_sync(0xffffffffu, rm[i], off));

            float sc[2], rs[2];
#pragma unroll
            for (int i = 0; i < 2; i++) {
                const float mn = fmaxf(m[i], rm[i]);
                sc[i] = __expf(m[i] - mn);
                m[i] = mn;
                float r = 0.f;
#pragma unroll
                for (int j = 0; j < 4; j++) {
                    const float pv = __expf(s[i][j] - m[i]);
                    s[i][j] = pv;
                    r += pv;
                }
                rs[i] = r;
            }
#pragma unroll
            for (int off = 8; off > 0; off >>= 1)
#pragma unroll
                for (int i = 0; i < 2; i++)
                    rs[i] += __shfl_xor_sync(0xffffffffu, rs[i], off);
#pragma unroll
            for (int i = 0; i < 2; i++) {
                l[i] = l[i] * sc[i] + rs[i];
#pragma unroll
                for (int j = 0; j < 4; j++) acc[i][j] *= sc[i];
            }

            __syncthreads();
#pragma unroll
            for (int i = 0; i < 2; i++)
                *(float4*)&KP[ty*2 + i][tx*4] = make_float4(s[i][0], s[i][1], s[i][2], s[i][3]);
            __syncthreads();

#pragma unroll 8
            for (int kk = 0; kk < 64; kk += 4) {
                float4 a0 = *(float4*)&KP[ty*2 + 0][kk];
                float4 a1 = *(float4*)&KP[ty*2 + 1][kk];
                float ar[2][4] = {{a0.x,a0.y,a0.z,a0.w},{a1.x,a1.y,a1.z,a1.w}};
#pragma unroll
                for (int u = 0; u < 4; u++) {
                    float4 b = *(float4*)&Vs[kk + u][tx*4];
                    float br[4] = {b.x, b.y, b.z, b.w};
#pragma unroll
                    for (int i = 0; i < 2; i++)
#pragma unroll
                        for (int j = 0; j < 4; j++)
                            acc[i][j] = fmaf(ar[i][u], br[j], acc[i][j]);
                }
            }
        }

        const int base = (bh * 4 + kc) * 32;
#pragma unroll
        for (int i = 0; i < 2; i++) {
            const int r = ty*2 + i;
            *(float4*)&g_pacc[(base + r) * 64 + tx*4] =
                make_float4(acc[i][0], acc[i][1], acc[i][2], acc[i][3]);
            if (tx == 0) { g_pm[base + r] = m[i]; g_pl[base + r] = l[i]; }
        }
    }
}

// ---------------- merge split-K partials -> fp16 g_ah ----------------
__global__ __launch_bounds__(256) void attn_gq_combine() {
    const int bh = blockIdx.x;
    const int b = bh >> 4, h = bh & 15;
    for (int idx = threadIdx.x; idx < 32 * 64; idx += 256) {
        const int r = idx >> 6, d = idx & 63;
        float M = -1e30f;
#pragma unroll
        for (int kc = 0; kc < 4; kc++)
            M = fmaxf(M, g_pm[(bh*4 + kc)*32 + r]);
        float l = 0.f, o = 0.f;
#pragma unroll
        for (int kc = 0; kc < 4; kc++) {
            const int p = (bh*4 + kc)*32 + r;
            const float w = __expf(g_pm[p] - M);
            l += w * g_pl[p];
            o += w * g_pacc[p * 64 + d];
        }
        g_ah[((size_t)b * T_SZ + (r << 6)) * DM + h * DH + d] = __float2half(o / l);
    }
}

// ---------------- launch ----------------
extern "C" void kernel_launch(void* const* d_in, const int* in_sizes, int n_in,
                              void* d_out, int out_size) {
    const float *x = 0;
    const float *Wqkv = 0;
    const float *Wout = 0;
    const float *bout = 0;
    for (int i = 0; i < n_in; i++) {
        switch (in_sizes[i]) {
            case B_SZ*T_SZ*DM: x    = (const float*)d_in[i]; break;
            case DM*3*DM:      Wqkv = (const float*)d_in[i]; break;
            case DM*DM:        Wout = (const float*)d_in[i]; break;
            case DM:           bout = (const float*)d_in[i]; break;
        }
    }
    float* out = (float*)d_out;

    cudaFuncSetAttribute(qkv_tc_kernel, cudaFuncAttributeMaxDynamicSharedMemorySize, GEMM_SMEM);
    cudaFuncSetAttribute(out_tc_kernel, cudaFuncAttributeMaxDynamicSharedMemorySize, GEMM_SMEM);
    cudaFuncSetAttribute(attn_fused_kernel, cudaFuncAttributeMaxDynamicSharedMemorySize, ATTN_SMEM);

    __half *xh, *wqh, *woh;
    cudaGetSymbolAddress((void**)&xh,  g_xh);
    cudaGetSymbolAddress((void**)&wqh, g_wqh);
    cudaGetSymbolAddress((void**)&woh, g_woh);

    rope_table_kernel<<<(T_SZ*HALF + 255) / 256, 256>>>();
    cvt_f16_kernel<<<(B_SZ*T_SZ*DM/8 + 255) / 256, 256>>>(x, xh, B_SZ*T_SZ*DM/8);
    cvt_f16_kernel<<<(DM*3*DM/8 + 255) / 256, 256>>>(Wqkv, wqh, DM*3*DM/8);
    cvt_f16_kernel<<<(DM*DM/8 + 255) / 256, 256>>>(Wout, woh, DM*DM/8);

    qkv_tc_kernel<<<dim3(3*DM/128, B_SZ*T_SZ/128), 256, GEMM_SMEM>>>();
    attn_fused_kernel<<<1024 + 256, 256, ATTN_SMEM>>>();
    attn_gq_combine<<<B_SZ*NH, 256>>>();
    out_tc_kernel<<<dim3(DM/128, B_SZ*T_SZ/128), 256, GEMM_SMEM>>>(bout, out);
}